// round 15
// baseline (speedup 1.0000x reference)
#include <cuda_runtime.h>
#include <cuda_bf16.h>
#include <cstdint>

// Problem constants
#define BB 4
#define TT 4096
#define DD 512

// ---------------- scratch (__device__ globals; no allocs allowed) ----------
__device__ __nv_bfloat16 g_xnb[(size_t)BB * TT * DD];  // normalized x, bf16
__device__ unsigned      g_m[(size_t)BB * TT];         // per-row max sim (order-encoded)

// ---- order-preserving float <-> uint for atomicMax ----
__device__ __forceinline__ unsigned ford(float f) {
    unsigned u = __float_as_uint(f);
    return (u & 0x80000000u) ? ~u : (u | 0x80000000u);
}
__device__ __forceinline__ float funord(unsigned u) {
    return __uint_as_float((u & 0x80000000u) ? (u ^ 0x80000000u) : ~u);
}

__device__ __forceinline__ uint32_t smem_u32(const void* p) {
    uint32_t a;
    asm("{ .reg .u64 t; cvta.to.shared.u64 t, %1; cvt.u32.u64 %0, t; }" : "=r"(a) : "l"(p));
    return a;
}

#define SWZ128(off) ((off) ^ (((off) >> 3) & 0x70))

#define CP_ASYNC16(sm, gm) \
    asm volatile("cp.async.cg.shared.global [%0], [%1], 16;" :: "r"(sm), "l"(gm) : "memory")
#define CP_COMMIT() asm volatile("cp.async.commit_group;" ::: "memory")
#define CP_WAIT1()  asm volatile("cp.async.wait_group 1;" ::: "memory")
#define CP_WAIT0()  asm volatile("cp.async.wait_group 0;" ::: "memory")

#define LDMATRIX_X4(r0, r1, r2, r3, addr) \
    asm volatile("ldmatrix.sync.aligned.m8n8.x4.shared.b16 {%0,%1,%2,%3}, [%4];" \
                 : "=r"(r0), "=r"(r1), "=r"(r2), "=r"(r3) : "r"(addr))

#define MMA_BF16(c0, c1, c2, c3, a0, a1, a2, a3, b0, b1) \
    asm volatile("mma.sync.aligned.m16n8k16.row.col.f32.bf16.bf16.f32 " \
                 "{%0,%1,%2,%3}, {%4,%5,%6,%7}, {%8,%9}, {%0,%1,%2,%3};" \
                 : "+f"(c0), "+f"(c1), "+f"(c2), "+f"(c3) \
                 : "r"(a0), "r"(a1), "r"(a2), "r"(a3), "r"(b0), "r"(b1))

// ============================================================
// Kernel A: per-row L2 normalize -> bf16; one warp per row.
// block = 256 threads = 8 rows; grid = B*T/8 = 2048.
// ============================================================
__global__ __launch_bounds__(256) void normalize_kernel(const float* __restrict__ x) {
    const int warp = threadIdx.x >> 5;
    const int lane = threadIdx.x & 31;
    const int row = blockIdx.x * 8 + warp;

    const float4* xin = reinterpret_cast<const float4*>(x + (size_t)row * DD);
    float4 v[4];
    float ss = 0.0f;
    #pragma unroll
    for (int i = 0; i < 4; i++) {
        v[i] = xin[lane + i * 32];
        ss += v[i].x * v[i].x + v[i].y * v[i].y + v[i].z * v[i].z + v[i].w * v[i].w;
    }
    #pragma unroll
    for (int off = 16; off > 0; off >>= 1)
        ss += __shfl_xor_sync(0xffffffffu, ss, off);
    float scale = 1.0f / fmaxf(sqrtf(ss), 1e-12f);

    uint2* xo = reinterpret_cast<uint2*>(g_xnb + (size_t)row * DD);
    #pragma unroll
    for (int i = 0; i < 4; i++) {
        __nv_bfloat162 p0 = __floats2bfloat162_rn(v[i].x * scale, v[i].y * scale);
        __nv_bfloat162 p1 = __floats2bfloat162_rn(v[i].z * scale, v[i].w * scale);
        uint2 o;
        o.x = *reinterpret_cast<unsigned*>(&p0);
        o.y = *reinterpret_cast<unsigned*>(&p1);
        xo[lane + i * 32] = o;
    }
    if (lane == 0) g_m[row] = ford(-2.0f);
}

// ============================================================
// Kernel B: mma.sync bf16 sim-max. CTA tile 128x128, 8 warps
// (4m x 2n), warp tile 32x64. K in 8 chunks of 64, 3-stage
// cp.async pipeline, 1 sync per chunk, folded swizzle addrs.
// Diagonal tiles: fully-masked warps skip ldmatrix+MMA.
// grid = (528 lower-tri pairs, B), 2 CTAs/SM.
// ============================================================
#define TM 128
#define KC 64
#define NCHUNK (DD / KC)        // 8
#define ROWB 128                // bytes per smem row (64 bf16)
#define BUF_BYTES (TM * ROWB)   // 16 KB per tile buffer
#define NSTAGE 3
#define SM_TOTAL (NSTAGE * 2 * BUF_BYTES)   // 96 KB

__global__ __launch_bounds__(256, 2) void simmax_mma_kernel() {
    extern __shared__ char smem[];
    const uint32_t smb = smem_u32(smem);
    const int tid = threadIdx.x;
    const int wid = tid >> 5;
    const int lane = tid & 31;

    // decode lower-triangular pair index -> (t_tile, s_tile)
    int p = blockIdx.x;
    int t_tile = (int)((sqrtf(8.0f * (float)p + 1.0f) - 1.0f) * 0.5f);
    while ((t_tile + 1) * (t_tile + 2) / 2 <= p) ++t_tile;
    while (t_tile * (t_tile + 1) / 2 > p) --t_tile;
    int s_tile = p - t_tile * (t_tile + 1) / 2;
    const int b = blockIdx.y;
    const int t0 = t_tile * TM;
    const int s0 = s_tile * TM;
    const bool diag = (s_tile == t_tile);

    const char* xa = reinterpret_cast<const char*>(g_xnb + ((size_t)b * TT + t0) * DD);
    const char* xb = reinterpret_cast<const char*>(g_xnb + ((size_t)b * TT + s0) * DD);

    const int warp_m = wid & 3;
    const int warp_n = wid >> 2;
    const int m0 = warp_m * 32;
    const int n0 = warp_n * 64;

    // On diagonal tiles a warp contributes iff some (row,col) with col<row
    // exists in its 32x64 patch: n0 < m0+31. Warps (0,1),(1,1) are fully
    // masked there and skip all tensor work (still load + barrier).
    const bool wactive = !diag || (n0 < m0 + 31);

    float acc[2][8][4];
    #pragma unroll
    for (int mi = 0; mi < 2; mi++)
        #pragma unroll
        for (int nj = 0; nj < 8; nj++)
            #pragma unroll
            for (int r = 0; r < 4; r++) acc[mi][nj][r] = 0.0f;

    // ---- folded swizzle base addresses (within a tile buffer) ----
    uint32_t a_sw[2], b_sw[4];
    {
        const int a_half16 = (lane >> 4) * 16;
        #pragma unroll
        for (int mi = 0; mi < 2; mi++) {
            uint32_t rb = (uint32_t)((m0 + mi * 16 + (lane & 15)) * ROWB);
            uint32_t mask = (rb >> 3) & 0x70;
            a_sw[mi] = rb | (a_half16 ^ mask);
        }
        const int b_half16 = ((lane >> 3) & 1) * 16;
        #pragma unroll
        for (int nt = 0; nt < 4; nt++) {
            uint32_t rb = (uint32_t)((n0 + nt * 16 + (lane & 7) + ((lane & 16) ? 8 : 0)) * ROWB);
            uint32_t mask = (rb >> 3) & 0x70;
            b_sw[nt] = rb | (b_half16 ^ mask);
        }
    }

    // loader-side precompute
    const int ld_row = tid >> 3;
    const int ld_seg = tid & 7;
    uint32_t ld_sw[4];
    const char* ld_ga[4];
    const char* ld_gb[4];
    #pragma unroll
    for (int q = 0; q < 4; q++) {
        int row = ld_row + q * 32;
        ld_sw[q] = SWZ128((uint32_t)(row * ROWB + ld_seg * 16));
        ld_ga[q] = xa + (size_t)row * (DD * 2) + (size_t)(ld_seg * 8) * 2;
        ld_gb[q] = xb + (size_t)row * (DD * 2) + (size_t)(ld_seg * 8) * 2;
    }

    auto load_chunk = [&](int c) {
        const int buf = c % NSTAGE;
        const size_t koff = (size_t)(c * KC) * 2;
        const uint32_t a_base = smb + buf * 2 * BUF_BYTES;
        const uint32_t b_base = a_base + BUF_BYTES;
        #pragma unroll
        for (int q = 0; q < 4; q++) {
            CP_ASYNC16(a_base + ld_sw[q], ld_ga[q] + koff);
            CP_ASYNC16(b_base + ld_sw[q], ld_gb[q] + koff);
        }
        CP_COMMIT();
    };

    load_chunk(0);
    load_chunk(1);

    for (int c = 0; c < NCHUNK; c++) {
        const int buf = c % NSTAGE;
        if (c == NCHUNK - 1) { CP_WAIT0(); } else { CP_WAIT1(); }
        __syncthreads();
        if (c + 2 < NCHUNK) load_chunk(c + 2);

        const uint32_t a_base = smb + buf * 2 * BUF_BYTES;
        const uint32_t b_base = a_base + BUF_BYTES;

        if (wactive) {
            #pragma unroll
            for (int ks = 0; ks < KC / 16; ks++) {
                const uint32_t ks32 = (uint32_t)(ks * 32);
                uint32_t afr[2][4];
                #pragma unroll
                for (int mi = 0; mi < 2; mi++)
                    LDMATRIX_X4(afr[mi][0], afr[mi][1], afr[mi][2], afr[mi][3],
                                a_base + (a_sw[mi] ^ ks32));
                uint32_t bfr[4][4];
                #pragma unroll
                for (int nt = 0; nt < 4; nt++)
                    LDMATRIX_X4(bfr[nt][0], bfr[nt][1], bfr[nt][2], bfr[nt][3],
                                b_base + (b_sw[nt] ^ ks32));
                #pragma unroll
                for (int mi = 0; mi < 2; mi++)
                    #pragma unroll
                    for (int nt = 0; nt < 4; nt++) {
                        MMA_BF16(acc[mi][nt * 2][0], acc[mi][nt * 2][1],
                                 acc[mi][nt * 2][2], acc[mi][nt * 2][3],
                                 afr[mi][0], afr[mi][1], afr[mi][2], afr[mi][3],
                                 bfr[nt][0], bfr[nt][1]);
                        MMA_BF16(acc[mi][nt * 2 + 1][0], acc[mi][nt * 2 + 1][1],
                                 acc[mi][nt * 2 + 1][2], acc[mi][nt * 2 + 1][3],
                                 afr[mi][0], afr[mi][1], afr[mi][2], afr[mi][3],
                                 bfr[nt][2], bfr[nt][3]);
                    }
            }
        }
    }

    // ---- epilogue: row max from accumulators (inactive warps skip) ----
    if (wactive) {
        #pragma unroll
        for (int mi = 0; mi < 2; mi++) {
            int row_lo = m0 + mi * 16 + (lane >> 2);
            int row_hi = row_lo + 8;
            float mx0 = -3.0f, mx1 = -3.0f;
            #pragma unroll
            for (int nj = 0; nj < 8; nj++) {
                int col = n0 + nj * 8 + (lane & 3) * 2;
                if (!diag || col     < row_lo) mx0 = fmaxf(mx0, acc[mi][nj][0]);
                if (!diag || col + 1 < row_lo) mx0 = fmaxf(mx0, acc[mi][nj][1]);
                if (!diag || col     < row_hi) mx1 = fmaxf(mx1, acc[mi][nj][2]);
                if (!diag || col + 1 < row_hi) mx1 = fmaxf(mx1, acc[mi][nj][3]);
            }
            mx0 = fmaxf(mx0, __shfl_xor_sync(0xffffffffu, mx0, 1));
            mx0 = fmaxf(mx0, __shfl_xor_sync(0xffffffffu, mx0, 2));
            mx1 = fmaxf(mx1, __shfl_xor_sync(0xffffffffu, mx1, 1));
            mx1 = fmaxf(mx1, __shfl_xor_sync(0xffffffffu, mx1, 2));
            if ((lane & 3) == 0) {
                if (mx0 > -2.5f) atomicMax(&g_m[(size_t)b * TT + t0 + row_lo], ford(mx0));
                if (mx1 > -2.5f) atomicMax(&g_m[(size_t)b * TT + t0 + row_hi], ford(mx1));
            }
        }
    }
}

// ============================================================
// Kernel C: gate + GELU epilogue. x*sigmoid(2c(x+0.044715x^3))
// with __expf + __fdividef (MUFU path, no IEEE div).
// ============================================================
__global__ void gate_gelu_kernel(const float* __restrict__ x,
                                 const float* __restrict__ log_alpha,
                                 float* __restrict__ out) {
    size_t idx = (size_t)blockIdx.x * blockDim.x + threadIdx.x;
    size_t total4 = (size_t)BB * TT * DD / 4;
    if (idx >= total4) return;

    float la = *log_alpha;
    float alpha = (la > 20.0f) ? la : log1pf(expf(la));

    size_t row = idx / (DD / 4);
    float m = funord(g_m[row]);
    m = fmaxf(m, -1.0f);
    float gate = 1.0f + alpha * 0.5f * (1.0f - m);

    float4 v = reinterpret_cast<const float4*>(x)[idx];
    const float c2 = 2.0f * 0.7978845608028654f;   // 2*sqrt(2/pi)
    float r[4] = {v.x, v.y, v.z, v.w};
    #pragma unroll
    for (int i = 0; i < 4; i++) {
        float xv = r[i] * gate;
        float u = c2 * (xv + 0.044715f * xv * xv * xv);
        r[i] = __fdividef(xv, 1.0f + __expf(-u));   // == 0.5*xv*(1+tanh(...))
    }
    float4 o = {r[0], r[1], r[2], r[3]};
    reinterpret_cast<float4*>(out)[idx] = o;
}

extern "C" void kernel_launch(void* const* d_in, const int* in_sizes, int n_in,
                              void* d_out, int out_size) {
    const float* x  = (const float*)d_in[0];
    const float* la = (const float*)d_in[1];
    float* out = (float*)d_out;

    normalize_kernel<<<BB * TT / 8, 256>>>(x);

    cudaFuncSetAttribute(simmax_mma_kernel,
                         cudaFuncAttributeMaxDynamicSharedMemorySize, SM_TOTAL);
    int ntiles = (TT / TM) * (TT / TM + 1) / 2;   // 528
    dim3 grid(ntiles, BB);
    simmax_mma_kernel<<<grid, 256, SM_TOTAL>>>();

    size_t total4 = (size_t)BB * TT * DD / 4;
    int threads = 256;
    int blocks = (int)((total4 + threads - 1) / threads);
    gate_gelu_kernel<<<blocks, threads>>>(x, la, out);
}

// round 16
// speedup vs baseline: 1.1356x; 1.1356x over previous
#include <cuda_runtime.h>
#include <cuda_bf16.h>
#include <cstdint>

// Problem constants
#define BB 4
#define TT 4096
#define DD 512

// ---------------- scratch (__device__ globals; no allocs allowed) ----------
__device__ __nv_bfloat16 g_xnb[(size_t)BB * TT * DD];  // normalized x, bf16
__device__ unsigned      g_m[(size_t)BB * TT];         // per-row max sim (order-encoded)

// ---- order-preserving float <-> uint for atomicMax ----
__device__ __forceinline__ unsigned ford(float f) {
    unsigned u = __float_as_uint(f);
    return (u & 0x80000000u) ? ~u : (u | 0x80000000u);
}
__device__ __forceinline__ float funord(unsigned u) {
    return __uint_as_float((u & 0x80000000u) ? (u ^ 0x80000000u) : ~u);
}

__device__ __forceinline__ uint32_t smem_u32(const void* p) {
    uint32_t a;
    asm("{ .reg .u64 t; cvta.to.shared.u64 t, %1; cvt.u32.u64 %0, t; }" : "=r"(a) : "l"(p));
    return a;
}

#define SWZ128(off) ((off) ^ (((off) >> 3) & 0x70))

#define CP_ASYNC16(sm, gm) \
    asm volatile("cp.async.cg.shared.global [%0], [%1], 16;" :: "r"(sm), "l"(gm) : "memory")
#define CP_COMMIT() asm volatile("cp.async.commit_group;" ::: "memory")
#define CP_WAIT1()  asm volatile("cp.async.wait_group 1;" ::: "memory")
#define CP_WAIT0()  asm volatile("cp.async.wait_group 0;" ::: "memory")

#define LDMATRIX_X4(r0, r1, r2, r3, addr) \
    asm volatile("ldmatrix.sync.aligned.m8n8.x4.shared.b16 {%0,%1,%2,%3}, [%4];" \
                 : "=r"(r0), "=r"(r1), "=r"(r2), "=r"(r3) : "r"(addr))

#define MMA_BF16(c0, c1, c2, c3, a0, a1, a2, a3, b0, b1) \
    asm volatile("mma.sync.aligned.m16n8k16.row.col.f32.bf16.bf16.f32 " \
                 "{%0,%1,%2,%3}, {%4,%5,%6,%7}, {%8,%9}, {%0,%1,%2,%3};" \
                 : "+f"(c0), "+f"(c1), "+f"(c2), "+f"(c3) \
                 : "r"(a0), "r"(a1), "r"(a2), "r"(a3), "r"(b0), "r"(b1))

// ============================================================
// Kernel A: per-row L2 normalize -> bf16; one warp per row.
// block = 256 threads = 8 rows; grid = B*T/8 = 2048.
// ============================================================
__global__ __launch_bounds__(256) void normalize_kernel(const float* __restrict__ x) {
    const int warp = threadIdx.x >> 5;
    const int lane = threadIdx.x & 31;
    const int row = blockIdx.x * 8 + warp;

    const float4* xin = reinterpret_cast<const float4*>(x + (size_t)row * DD);
    float4 v[4];
    float ss = 0.0f;
    #pragma unroll
    for (int i = 0; i < 4; i++) {
        v[i] = xin[lane + i * 32];
        ss += v[i].x * v[i].x + v[i].y * v[i].y + v[i].z * v[i].z + v[i].w * v[i].w;
    }
    #pragma unroll
    for (int off = 16; off > 0; off >>= 1)
        ss += __shfl_xor_sync(0xffffffffu, ss, off);
    float scale = 1.0f / fmaxf(sqrtf(ss), 1e-12f);

    uint2* xo = reinterpret_cast<uint2*>(g_xnb + (size_t)row * DD);
    #pragma unroll
    for (int i = 0; i < 4; i++) {
        __nv_bfloat162 p0 = __floats2bfloat162_rn(v[i].x * scale, v[i].y * scale);
        __nv_bfloat162 p1 = __floats2bfloat162_rn(v[i].z * scale, v[i].w * scale);
        uint2 o;
        o.x = *reinterpret_cast<unsigned*>(&p0);
        o.y = *reinterpret_cast<unsigned*>(&p1);
        xo[lane + i * 32] = o;
    }
    if (lane == 0) g_m[row] = ford(-2.0f);
}

// ============================================================
// Kernel B: mma.sync bf16 sim-max. CTA tile 128x128, 8 warps
// (4m x 2n), warp tile 32x64. K in 8 chunks of 64, 3-stage
// cp.async pipeline, 1 sync per chunk, folded swizzle addrs.
// grid = (528 lower-tri pairs, B), 2 CTAs/SM.
// ============================================================
#define TM 128
#define KC 64
#define NCHUNK (DD / KC)        // 8
#define ROWB 128                // bytes per smem row (64 bf16)
#define BUF_BYTES (TM * ROWB)   // 16 KB per tile buffer
#define NSTAGE 3
#define SM_TOTAL (NSTAGE * 2 * BUF_BYTES)   // 96 KB

__global__ __launch_bounds__(256, 2) void simmax_mma_kernel() {
    extern __shared__ char smem[];
    const uint32_t smb = smem_u32(smem);
    const int tid = threadIdx.x;
    const int wid = tid >> 5;
    const int lane = tid & 31;

    // decode lower-triangular pair index -> (t_tile, s_tile)
    int p = blockIdx.x;
    int t_tile = (int)((sqrtf(8.0f * (float)p + 1.0f) - 1.0f) * 0.5f);
    while ((t_tile + 1) * (t_tile + 2) / 2 <= p) ++t_tile;
    while (t_tile * (t_tile + 1) / 2 > p) --t_tile;
    int s_tile = p - t_tile * (t_tile + 1) / 2;
    const int b = blockIdx.y;
    const int t0 = t_tile * TM;
    const int s0 = s_tile * TM;
    const bool diag = (s_tile == t_tile);

    const char* xa = reinterpret_cast<const char*>(g_xnb + ((size_t)b * TT + t0) * DD);
    const char* xb = reinterpret_cast<const char*>(g_xnb + ((size_t)b * TT + s0) * DD);

    const int warp_m = wid & 3;
    const int warp_n = wid >> 2;
    const int m0 = warp_m * 32;
    const int n0 = warp_n * 64;

    float acc[2][8][4];
    #pragma unroll
    for (int mi = 0; mi < 2; mi++)
        #pragma unroll
        for (int nj = 0; nj < 8; nj++)
            #pragma unroll
            for (int r = 0; r < 4; r++) acc[mi][nj][r] = 0.0f;

    // ---- folded swizzle base addresses (within a tile buffer) ----
    uint32_t a_sw[2], b_sw[4];
    {
        const int a_half16 = (lane >> 4) * 16;
        #pragma unroll
        for (int mi = 0; mi < 2; mi++) {
            uint32_t rb = (uint32_t)((m0 + mi * 16 + (lane & 15)) * ROWB);
            uint32_t mask = (rb >> 3) & 0x70;
            a_sw[mi] = rb | (a_half16 ^ mask);
        }
        const int b_half16 = ((lane >> 3) & 1) * 16;
        #pragma unroll
        for (int nt = 0; nt < 4; nt++) {
            uint32_t rb = (uint32_t)((n0 + nt * 16 + (lane & 7) + ((lane & 16) ? 8 : 0)) * ROWB);
            uint32_t mask = (rb >> 3) & 0x70;
            b_sw[nt] = rb | (b_half16 ^ mask);
        }
    }

    // loader-side precompute
    const int ld_row = tid >> 3;
    const int ld_seg = tid & 7;
    uint32_t ld_sw[4];
    const char* ld_ga[4];
    const char* ld_gb[4];
    #pragma unroll
    for (int q = 0; q < 4; q++) {
        int row = ld_row + q * 32;
        ld_sw[q] = SWZ128((uint32_t)(row * ROWB + ld_seg * 16));
        ld_ga[q] = xa + (size_t)row * (DD * 2) + (size_t)(ld_seg * 8) * 2;
        ld_gb[q] = xb + (size_t)row * (DD * 2) + (size_t)(ld_seg * 8) * 2;
    }

    auto load_chunk = [&](int c) {
        const int buf = c % NSTAGE;
        const size_t koff = (size_t)(c * KC) * 2;
        const uint32_t a_base = smb + buf * 2 * BUF_BYTES;
        const uint32_t b_base = a_base + BUF_BYTES;
        #pragma unroll
        for (int q = 0; q < 4; q++) {
            CP_ASYNC16(a_base + ld_sw[q], ld_ga[q] + koff);
            CP_ASYNC16(b_base + ld_sw[q], ld_gb[q] + koff);
        }
        CP_COMMIT();
    };

    load_chunk(0);
    load_chunk(1);

    for (int c = 0; c < NCHUNK; c++) {
        const int buf = c % NSTAGE;
        if (c == NCHUNK - 1) { CP_WAIT0(); } else { CP_WAIT1(); }
        __syncthreads();
        if (c + 2 < NCHUNK) load_chunk(c + 2);

        const uint32_t a_base = smb + buf * 2 * BUF_BYTES;
        const uint32_t b_base = a_base + BUF_BYTES;

        #pragma unroll
        for (int ks = 0; ks < KC / 16; ks++) {
            const uint32_t ks32 = (uint32_t)(ks * 32);
            uint32_t afr[2][4];
            #pragma unroll
            for (int mi = 0; mi < 2; mi++)
                LDMATRIX_X4(afr[mi][0], afr[mi][1], afr[mi][2], afr[mi][3],
                            a_base + (a_sw[mi] ^ ks32));
            uint32_t bfr[4][4];
            #pragma unroll
            for (int nt = 0; nt < 4; nt++)
                LDMATRIX_X4(bfr[nt][0], bfr[nt][1], bfr[nt][2], bfr[nt][3],
                            b_base + (b_sw[nt] ^ ks32));
            #pragma unroll
            for (int mi = 0; mi < 2; mi++)
                #pragma unroll
                for (int nt = 0; nt < 4; nt++) {
                    MMA_BF16(acc[mi][nt * 2][0], acc[mi][nt * 2][1],
                             acc[mi][nt * 2][2], acc[mi][nt * 2][3],
                             afr[mi][0], afr[mi][1], afr[mi][2], afr[mi][3],
                             bfr[nt][0], bfr[nt][1]);
                    MMA_BF16(acc[mi][nt * 2 + 1][0], acc[mi][nt * 2 + 1][1],
                             acc[mi][nt * 2 + 1][2], acc[mi][nt * 2 + 1][3],
                             afr[mi][0], afr[mi][1], afr[mi][2], afr[mi][3],
                             bfr[nt][2], bfr[nt][3]);
                }
        }
    }

    // ---- epilogue: row max from accumulators ----
    #pragma unroll
    for (int mi = 0; mi < 2; mi++) {
        int row_lo = m0 + mi * 16 + (lane >> 2);
        int row_hi = row_lo + 8;
        float mx0 = -3.0f, mx1 = -3.0f;
        #pragma unroll
        for (int nj = 0; nj < 8; nj++) {
            int col = n0 + nj * 8 + (lane & 3) * 2;
            if (!diag || col     < row_lo) mx0 = fmaxf(mx0, acc[mi][nj][0]);
            if (!diag || col + 1 < row_lo) mx0 = fmaxf(mx0, acc[mi][nj][1]);
            if (!diag || col     < row_hi) mx1 = fmaxf(mx1, acc[mi][nj][2]);
            if (!diag || col + 1 < row_hi) mx1 = fmaxf(mx1, acc[mi][nj][3]);
        }
        mx0 = fmaxf(mx0, __shfl_xor_sync(0xffffffffu, mx0, 1));
        mx0 = fmaxf(mx0, __shfl_xor_sync(0xffffffffu, mx0, 2));
        mx1 = fmaxf(mx1, __shfl_xor_sync(0xffffffffu, mx1, 1));
        mx1 = fmaxf(mx1, __shfl_xor_sync(0xffffffffu, mx1, 2));
        if ((lane & 3) == 0) {
            if (mx0 > -2.5f) atomicMax(&g_m[(size_t)b * TT + t0 + row_lo], ford(mx0));
            if (mx1 > -2.5f) atomicMax(&g_m[(size_t)b * TT + t0 + row_hi], ford(mx1));
        }
    }
}

// ============================================================
// Kernel C: gate + GELU epilogue. x*sigmoid(2c(x+0.044715x^3))
// with __expf + __fdividef (MUFU path, no IEEE div).
// ============================================================
__global__ void gate_gelu_kernel(const float* __restrict__ x,
                                 const float* __restrict__ log_alpha,
                                 float* __restrict__ out) {
    size_t idx = (size_t)blockIdx.x * blockDim.x + threadIdx.x;
    size_t total4 = (size_t)BB * TT * DD / 4;
    if (idx >= total4) return;

    float la = *log_alpha;
    float alpha = (la > 20.0f) ? la : log1pf(expf(la));

    size_t row = idx / (DD / 4);
    float m = funord(g_m[row]);
    m = fmaxf(m, -1.0f);
    float gate = 1.0f + alpha * 0.5f * (1.0f - m);

    float4 v = reinterpret_cast<const float4*>(x)[idx];
    const float c2 = 2.0f * 0.7978845608028654f;   // 2*sqrt(2/pi)
    float r[4] = {v.x, v.y, v.z, v.w};
    #pragma unroll
    for (int i = 0; i < 4; i++) {
        float xv = r[i] * gate;
        float u = c2 * (xv + 0.044715f * xv * xv * xv);
        r[i] = __fdividef(xv, 1.0f + __expf(-u));   // == 0.5*xv*(1+tanh(...))
    }
    float4 o = {r[0], r[1], r[2], r[3]};
    reinterpret_cast<float4*>(out)[idx] = o;
}

extern "C" void kernel_launch(void* const* d_in, const int* in_sizes, int n_in,
                              void* d_out, int out_size) {
    const float* x  = (const float*)d_in[0];
    const float* la = (const float*)d_in[1];
    float* out = (float*)d_out;

    normalize_kernel<<<BB * TT / 8, 256>>>(x);

    cudaFuncSetAttribute(simmax_mma_kernel,
                         cudaFuncAttributeMaxDynamicSharedMemorySize, SM_TOTAL);
    int ntiles = (TT / TM) * (TT / TM + 1) / 2;   // 528
    dim3 grid(ntiles, BB);
    simmax_mma_kernel<<<grid, 256, SM_TOTAL>>>();

    size_t total4 = (size_t)BB * TT * DD / 4;
    int threads = 256;
    int blocks = (int)((total4 + threads - 1) / threads);
    gate_gelu_kernel<<<blocks, threads>>>(x, la, out);
}